// round 6
// baseline (speedup 1.0000x reference)
#include <cuda_runtime.h>
#include <math_constants.h>

// GCN_20753281975108: top-k masked neighbor aggregation.
// N=50000 nodes, M=32 mailbox, D=128 features, K=8 top-k.
// Output (f32): [ aggregate: N*D ][ selected_ids: N*K cast to f32 ]
//
// Persistent grid-stride version: one wave of 148x4 CTAs (no wave
// transitions); each warp processes ~11 nodes sequentially, letting
// loads of node i+1 overlap the shuffle/FMA drain of node i.

#define M_MB   32
#define D_FEAT 128
#define K_TOP  8
#define CHUNK  8

__global__ __launch_bounds__(256, 4)
void gcn_kernel(const float* __restrict__ interact,
                const float* __restrict__ initial,
                const float* __restrict__ src_info,
                const float* __restrict__ buffer,
                const float* __restrict__ keep_rate_p,
                const int* __restrict__ source_id,
                float* __restrict__ out_agg,
                float* __restrict__ out_ids,
                int n_nodes)
{
    const int lane = threadIdx.x & 31;
    const int warp0 = (blockIdx.x * blockDim.x + threadIdx.x) >> 5;
    const int warp_stride = (gridDim.x * blockDim.x) >> 5;

    const float keep = *keep_rate_p;

    for (int n = warp0; n < n_nodes; n += warp_stride) {

        const float s    = interact[(size_t)n * M_MB + lane];
        const float init = initial [(size_t)n * M_MB + lane];

        // ---- top-K via K iterative warp argmax (tie -> lower index) ----
        float v = s;
        int   my_sel = 0;
        bool  picked = false;
        #pragma unroll
        for (int k = 0; k < K_TOP; ++k) {
            float mv = v;
            int   mi = lane;
            #pragma unroll
            for (int off = 16; off > 0; off >>= 1) {
                float ov = __shfl_xor_sync(0xffffffffu, mv, off);
                int   oi = __shfl_xor_sync(0xffffffffu, mi, off);
                if (ov > mv || (ov == mv && oi < mi)) { mv = ov; mi = oi; }
            }
            if (lane == k)  my_sel = mi;
            if (lane == mi) { v = -CUDART_INF_F; picked = true; }
        }

        // ---- selected ids: store early (independent of heavy loop) ----
        if (lane < K_TOP) {
            const int id = source_id[(size_t)n * M_MB + my_sel];
            out_ids[(size_t)n * K_TOP + lane] = (float)id;  // exact: id < 2^24
        }

        // ---- pseudo-adjacency (non-topk sigmoid term == 0 in fp32) ----
        const float sig = picked ? (1.0f / (1.0f + expf(-s))) : 0.0f;
        const float adj = (1.0f - keep) * sig + keep * init;

        // coefficient = sum(adj) + 1
        float c = adj;
        #pragma unroll
        for (int off = 16; off > 0; off >>= 1)
            c += __shfl_xor_sync(0xffffffffu, c, off);
        const float inv_c = 1.0f / (c + 1.0f);

        // ---- weighted neighbor reduction, 8-deep load batches ----
        const float4* __restrict__ src4 =
            reinterpret_cast<const float4*>(src_info + (size_t)n * M_MB * D_FEAT);

        float4 acc = make_float4(0.f, 0.f, 0.f, 0.f);
        #pragma unroll
        for (int cch = 0; cch < M_MB / CHUNK; ++cch) {
            float4 xv[CHUNK];
            #pragma unroll
            for (int j = 0; j < CHUNK; ++j)
                xv[j] = src4[(cch * CHUNK + j) * (D_FEAT / 4) + lane];
            #pragma unroll
            for (int j = 0; j < CHUNK; ++j) {
                const float a = __shfl_sync(0xffffffffu, adj, cch * CHUNK + j);
                acc.x = fmaf(a, xv[j].x, acc.x);
                acc.y = fmaf(a, xv[j].y, acc.y);
                acc.z = fmaf(a, xv[j].z, acc.z);
                acc.w = fmaf(a, xv[j].w, acc.w);
            }
        }

        const float4 b =
            reinterpret_cast<const float4*>(buffer + (size_t)n * D_FEAT)[lane];
        acc.x = (acc.x + b.x) * inv_c;
        acc.y = (acc.y + b.y) * inv_c;
        acc.z = (acc.z + b.z) * inv_c;
        acc.w = (acc.w + b.w) * inv_c;

        reinterpret_cast<float4*>(out_agg + (size_t)n * D_FEAT)[lane] = acc;
    }
}

extern "C" void kernel_launch(void* const* d_in, const int* in_sizes, int n_in,
                              void* d_out, int out_size)
{
    const float* interact = (const float*)d_in[0];
    const float* initial  = (const float*)d_in[1];
    const float* src_info = (const float*)d_in[2];
    const float* buffer   = (const float*)d_in[3];
    const float* keep     = (const float*)d_in[5];
    const int*   sid      = (const int*)d_in[6];

    const int n_nodes = in_sizes[0] / M_MB;   // 50000

    float* out_agg = (float*)d_out;
    float* out_ids = out_agg + (size_t)n_nodes * D_FEAT;

    // one resident wave: 148 SMs x 4 CTAs (64 regs, 256 thr)
    const int blocks = 148 * 4;
    gcn_kernel<<<blocks, 256>>>(
        interact, initial, src_info, buffer, keep, sid,
        out_agg, out_ids, n_nodes);
}

// round 7
// speedup vs baseline: 1.1182x; 1.1182x over previous
#include <cuda_runtime.h>
#include <math_constants.h>

// GCN_20753281975108: top-k masked neighbor aggregation.
// N=50000 nodes, M=32 mailbox, D=128 features, K=8 top-k.
// Output (f32): [ aggregate: N*D ][ selected_ids: N*K cast to f32 ]
//
// R4 config (best: one node per warp, occ ~91%, grid 6250) plus
// streaming cache hints: src_info is read-once (819 MB) and outputs are
// write-once -> __ldcs / __stcs to keep the dead stream from thrashing L2.

#define M_MB   32
#define D_FEAT 128
#define K_TOP  8

__global__ __launch_bounds__(256, 8)
void gcn_kernel(const float* __restrict__ interact,
                const float* __restrict__ initial,
                const float* __restrict__ src_info,
                const float* __restrict__ buffer,
                const float* __restrict__ keep_rate_p,
                const int* __restrict__ source_id,
                float* __restrict__ out_agg,
                float* __restrict__ out_ids,
                int n_nodes)
{
    const int warp_global = (blockIdx.x * blockDim.x + threadIdx.x) >> 5;
    if (warp_global >= n_nodes) return;
    const int lane = threadIdx.x & 31;
    const int n = warp_global;

    const float keep = *keep_rate_p;

    const float s    = interact[(size_t)n * M_MB + lane];
    const float init = initial [(size_t)n * M_MB + lane];

    // ---- top-K via K iterative warp argmax (tie -> lower index) ----
    float v = s;
    int   my_sel = 0;
    bool  picked = false;
    #pragma unroll
    for (int k = 0; k < K_TOP; ++k) {
        float mv = v;
        int   mi = lane;
        #pragma unroll
        for (int off = 16; off > 0; off >>= 1) {
            float ov = __shfl_xor_sync(0xffffffffu, mv, off);
            int   oi = __shfl_xor_sync(0xffffffffu, mi, off);
            if (ov > mv || (ov == mv && oi < mi)) { mv = ov; mi = oi; }
        }
        if (lane == k)  my_sel = mi;
        if (lane == mi) { v = -CUDART_INF_F; picked = true; }
    }

    // ---- selected ids: store early, streaming ----
    if (lane < K_TOP) {
        const int id = source_id[(size_t)n * M_MB + my_sel];
        __stcs(&out_ids[(size_t)n * K_TOP + lane], (float)id);  // exact: id < 2^24
    }

    // ---- pseudo-adjacency (non-topk sigmoid term == 0 in fp32) ----
    const float sig = picked ? (1.0f / (1.0f + expf(-s))) : 0.0f;
    const float adj = (1.0f - keep) * sig + keep * init;

    // coefficient = sum(adj) + 1
    float c = adj;
    #pragma unroll
    for (int off = 16; off > 0; off >>= 1)
        c += __shfl_xor_sync(0xffffffffu, c, off);
    const float inv_c = 1.0f / (c + 1.0f);

    // ---- weighted neighbor reduction: acc[d] = sum_m adj[m]*src[n,m,d] ----
    const float4* __restrict__ src4 =
        reinterpret_cast<const float4*>(src_info + (size_t)n * M_MB * D_FEAT);

    float4 acc = make_float4(0.f, 0.f, 0.f, 0.f);
    #pragma unroll
    for (int m = 0; m < M_MB; ++m) {
        const float  a = __shfl_sync(0xffffffffu, adj, m);
        const float4 x = __ldcs(&src4[m * (D_FEAT / 4) + lane]);  // evict-first
        acc.x = fmaf(a, x.x, acc.x);
        acc.y = fmaf(a, x.y, acc.y);
        acc.z = fmaf(a, x.z, acc.z);
        acc.w = fmaf(a, x.w, acc.w);
    }

    const float4 b =
        reinterpret_cast<const float4*>(buffer + (size_t)n * D_FEAT)[lane];
    acc.x = (acc.x + b.x) * inv_c;
    acc.y = (acc.y + b.y) * inv_c;
    acc.z = (acc.z + b.z) * inv_c;
    acc.w = (acc.w + b.w) * inv_c;

    __stcs(&reinterpret_cast<float4*>(out_agg + (size_t)n * D_FEAT)[lane], acc);
}

extern "C" void kernel_launch(void* const* d_in, const int* in_sizes, int n_in,
                              void* d_out, int out_size)
{
    const float* interact = (const float*)d_in[0];
    const float* initial  = (const float*)d_in[1];
    const float* src_info = (const float*)d_in[2];
    const float* buffer   = (const float*)d_in[3];
    const float* keep     = (const float*)d_in[5];
    const int*   sid      = (const int*)d_in[6];

    const int n_nodes = in_sizes[0] / M_MB;   // 50000

    float* out_agg = (float*)d_out;
    float* out_ids = out_agg + (size_t)n_nodes * D_FEAT;

    const int warps_per_block = 8;            // 256 threads
    const int blocks = (n_nodes + warps_per_block - 1) / warps_per_block;
    gcn_kernel<<<blocks, warps_per_block * 32>>>(
        interact, initial, src_info, buffer, keep, sid,
        out_agg, out_ids, n_nodes);
}